// round 14
// baseline (speedup 1.0000x reference)
#include <cuda_runtime.h>
#include <cuda_bf16.h>
#include <math.h>
#include <stdint.h>
#include <stddef.h>

// BornCollapseSampler — bf16 split-precision GEMM via mma.sync (HMMA.16816)
// + fused 3-pass sampler.
// R12: GEMM 4-buffer ring w/ single sync + early prefetch (occ 1);
//      sampler fused from 6 row-passes to 3.
// R13: fix compile error (stray __float_as_float artifact in float_key).
//
// Output layout (float32): [0,BSV) logits | [BSV,2BSV) log_probs |
//                          [2BSV,2BSV+512) tokens | then probs.

#define BDIM 512
#define VDIM 50257
#define KDIM 1024
#define TOPK 50
#define TOPP 0.95f
#define THREEFRY_PARTITIONABLE 1

#define NT   393            // n tiles of 128 (pad to 50304)
#define NPAD (NT * 128)
#define KC   32             // k chunks of 64 bf16 per 2048-col half

static const long long BSV = (long long)BDIM * VDIM;

// scratch: SW128-swizzled tile blocks, 128 rows x 64 bf16 = 16KB = 1024 uint4
__device__ uint4 g_Ahi[KC * 4 * 1024];                 // [kc][m_tile][block]
__device__ uint4 g_Alo[KC * 4 * 1024];
__device__ uint4 g_Bhi[(size_t)NT * KC * 1024];        // [nt][kc][block]
__device__ uint4 g_Blo[(size_t)NT * KC * 1024];

// ---------------------------------------------------------------------------
// threefry2x32 key (0,42)
// ---------------------------------------------------------------------------
__device__ __forceinline__ uint32_t rotl32(uint32_t x, int r) {
    return (x << r) | (x >> (32 - r));
}
__device__ __forceinline__ uint2 tf2x32(uint32_t x0, uint32_t x1) {
    const uint32_t k0 = 0u, k1 = 42u;
    const uint32_t k2 = k0 ^ k1 ^ 0x1BD11BDAu;
    x0 += k0; x1 += k1;
#define TFR(r) { x0 += x1; x1 = rotl32(x1, r); x1 ^= x0; }
    TFR(13) TFR(15) TFR(26) TFR(6)   x0 += k1; x1 += k2 + 1u;
    TFR(17) TFR(29) TFR(16) TFR(24)  x0 += k2; x1 += k0 + 2u;
    TFR(13) TFR(15) TFR(26) TFR(6)   x0 += k0; x1 += k1 + 3u;
    TFR(17) TFR(29) TFR(16) TFR(24)  x0 += k1; x1 += k2 + 4u;
    TFR(13) TFR(15) TFR(26) TFR(6)   x0 += k2; x1 += k0 + 5u;
#undef TFR
    return make_uint2(x0, x1);
}
__device__ __forceinline__ float gumbel_at(unsigned long long i) {
    uint32_t bits;
#if THREEFRY_PARTITIONABLE
    uint2 o = tf2x32((uint32_t)(i >> 32), (uint32_t)i);
    bits = o.x ^ o.y;
#else
    const unsigned long long HALF = ((unsigned long long)BDIM * VDIM) / 2ull;
    if (i < HALF) { uint2 o = tf2x32((uint32_t)i, (uint32_t)(i + HALF)); bits = o.x; }
    else          { uint2 o = tf2x32((uint32_t)(i - HALF), (uint32_t)i); bits = o.y; }
#endif
    float f = __uint_as_float((bits >> 9) | 0x3f800000u) - 1.0f;
    float u = fmaxf(f, 1.1754943508222875e-38f);
    return -logf(-logf(u));
}

// ---------------------------------------------------------------------------
// Conversion: fp32 -> (hi, lo) bf16 into SW128-swizzled tile blocks
// ---------------------------------------------------------------------------
__device__ __forceinline__ uint32_t sw128(uint32_t b) { return b ^ ((b >> 3) & 0x70u); }

union U16x8 { uint4 v; unsigned short s[8]; };

__global__ void __launch_bounds__(256) convA_kernel(const float* __restrict__ Pr,
                                                    const float* __restrict__ Pi)
{
    int g = blockIdx.x * 256 + threadIdx.x;   // 512 rows x 256 groups
    int row = g >> 8, grp = g & 255;
    int col0 = grp * 8;
    U16x8 uh, ul;
#pragma unroll
    for (int j = 0; j < 8; j++) {
        int c = col0 + j;
        float x = (c < KDIM) ? Pr[row * KDIM + c] : Pi[row * KDIM + c - KDIM];
        __nv_bfloat16 h = __float2bfloat16(x);
        __nv_bfloat16 l = __float2bfloat16(x - __bfloat162float(h));
        uh.s[j] = *reinterpret_cast<unsigned short*>(&h);
        ul.s[j] = *reinterpret_cast<unsigned short*>(&l);
    }
    int kc = col0 >> 6, cc = col0 & 63, m = row >> 7, r = row & 127;
    uint32_t byte = (uint32_t)(r * 128 + cc * 2);
    uint32_t unit = sw128(byte) >> 4;
    size_t idx = (size_t)(kc * 4 + m) * 1024 + unit;
    g_Ahi[idx] = uh.v;
    g_Alo[idx] = ul.v;
}

__global__ void __launch_bounds__(256) convB_kernel(const float* __restrict__ Wr,
                                                    const float* __restrict__ Wi)
{
    int row = blockIdx.x;          // 0..NPAD-1
    int col0 = threadIdx.x * 8;
    bool valid = (row < VDIM);
    U16x8 uh, ul;
#pragma unroll
    for (int j = 0; j < 8; j++) {
        int c = col0 + j;
        float x = 0.0f;
        if (valid) x = (c < KDIM) ? Wr[(size_t)row * KDIM + c]
                                  : Wi[(size_t)row * KDIM + c - KDIM];
        __nv_bfloat16 h = __float2bfloat16(x);
        __nv_bfloat16 l = __float2bfloat16(x - __bfloat162float(h));
        uh.s[j] = *reinterpret_cast<unsigned short*>(&h);
        ul.s[j] = *reinterpret_cast<unsigned short*>(&l);
    }
    int nt = row >> 7, kc = col0 >> 6, cc = col0 & 63, r = row & 127;
    uint32_t byte = (uint32_t)(r * 128 + cc * 2);
    uint32_t unit = sw128(byte) >> 4;
    size_t idx = (size_t)(nt * KC + kc) * 1024 + unit;
    g_Bhi[idx] = uh.v;
    g_Blo[idx] = ul.v;
}

// ---------------------------------------------------------------------------
// GEMM via mma.sync m16n8k16 bf16
// CTA: 128(M) x 128(N), 8 warps as 2(M) x 4(N), warp tile 64x32.
// 4-buffer cp.async ring, depth-2 prefetch, ONE syncthreads per iter:
//   iter c reads slots c%4 and (c+3)%4; issue(c+2) writes (c+2)%4 (disjoint).
// Chunks: even c -> {Ahi,Bhi}[kc] compute ahi*bhi;
// odd c -> {Alo,Blo}[kc] compute alo*bhi(prev buf) + ahi(prev buf)*blo.
// ---------------------------------------------------------------------------
__device__ __forceinline__ uint32_t smem_u32(const void* p) {
    uint32_t a;
    asm("{ .reg .u64 t; cvta.to.shared.u64 t, %1; cvt.u32.u64 %0, t; }"
        : "=r"(a) : "l"(p));
    return a;
}
__device__ __forceinline__ void cp16(uint32_t dst, const void* src) {
    asm volatile("cp.async.cg.shared.global [%0], [%1], 16;"
                 :: "r"(dst), "l"(src) : "memory");
}
__device__ __forceinline__ void cp_commit() {
    asm volatile("cp.async.commit_group;" ::: "memory");
}
__device__ __forceinline__ void ldsm4(uint32_t* r, uint32_t addr) {
    asm volatile("ldmatrix.sync.aligned.m8n8.x4.shared.b16 {%0,%1,%2,%3}, [%4];"
                 : "=r"(r[0]), "=r"(r[1]), "=r"(r[2]), "=r"(r[3]) : "r"(addr));
}
__device__ __forceinline__ void mma16816(float* d, const uint32_t* a,
                                         uint32_t b0, uint32_t b1) {
    asm volatile(
        "mma.sync.aligned.m16n8k16.row.col.f32.bf16.bf16.f32 "
        "{%0,%1,%2,%3}, {%4,%5,%6,%7}, {%8,%9}, {%0,%1,%2,%3};"
        : "+f"(d[0]), "+f"(d[1]), "+f"(d[2]), "+f"(d[3])
        : "r"(a[0]), "r"(a[1]), "r"(a[2]), "r"(a[3]), "r"(b0), "r"(b1));
}

#define STAGE_BYTES 32768
#define GEMM_SMEM (4 * STAGE_BYTES)    // 131072

__global__ void __launch_bounds__(256, 1)
gemm_mma_kernel(const float* __restrict__ bias, float* __restrict__ C)
{
    extern __shared__ char smem[];
    const uint32_t sb = smem_u32(smem);
    const int tid  = threadIdx.x;
    const int lane = tid & 31, w = tid >> 5;
    const int wm = w & 1, wn = w >> 1;
    const int nt = blockIdx.x >> 2, mt = blockIdx.x & 3;

    float acc[4][4][4];
#pragma unroll
    for (int i = 0; i < 4; i++)
#pragma unroll
        for (int j = 0; j < 4; j++)
#pragma unroll
            for (int r = 0; r < 4; r++) acc[i][j][r] = 0.0f;

    // per-lane ldmatrix row offsets
    const int rlo = lane & 15;           // row within 16
    const int khalf = (lane >> 4) * 16;  // 16B col half

    // -------- async chunk issuer --------
    auto issue = [&](int c) {
        const int kc = c >> 1;
        const uint4* As = ((c & 1) ? g_Alo : g_Ahi) + (size_t)(kc * 4 + mt) * 1024;
        const uint4* Bs = ((c & 1) ? g_Blo : g_Bhi) + ((size_t)nt * KC + kc) * 1024;
        const uint32_t d = sb + (uint32_t)(c & 3) * STAGE_BYTES;
#pragma unroll
        for (int i = 0; i < 4; i++) {
            int s = tid + i * 256;
            cp16(d + s * 16, As + s);
            cp16(d + 16384 + s * 16, Bs + s);
        }
        cp_commit();
    };

    // -------- compute one 64-k-bf16 pass --------
    auto compute = [&](uint32_t aBase, uint32_t bBase) {
#pragma unroll
        for (int kk = 0; kk < 4; kk++) {
            const uint32_t off = kk * 32 + khalf;
            uint32_t aR[4][4], bR[2][4];
#pragma unroll
            for (int i = 0; i < 4; i++) {
                int row = wm * 64 + i * 16 + rlo;
                uint32_t addr = aBase + row * 128 + (off ^ ((row & 7) << 4));
                ldsm4(aR[i], addr);
            }
#pragma unroll
            for (int j = 0; j < 2; j++) {
                int row = wn * 32 + j * 16 + rlo;
                uint32_t addr = bBase + row * 128 + (off ^ ((row & 7) << 4));
                ldsm4(bR[j], addr);
            }
#pragma unroll
            for (int i = 0; i < 4; i++)
#pragma unroll
                for (int jn = 0; jn < 4; jn++)
                    mma16816(acc[i][jn], aR[i],
                             bR[jn >> 1][jn & 1], bR[jn >> 1][2 + (jn & 1)]);
        }
    };

    issue(0);
    issue(1);

    for (int c = 0; c < 64; c++) {
        if (c < 63) asm volatile("cp.async.wait_group 1;" ::: "memory");
        else        asm volatile("cp.async.wait_group 0;" ::: "memory");
        __syncthreads();
        if (c + 2 < 64) issue(c + 2);    // writes slot (c+2)%4: disjoint from
                                         // this iter's read slots c%4,(c+3)%4
        const uint32_t cur = sb + (uint32_t)(c & 3) * STAGE_BYTES;
        if ((c & 1) == 0) {
            compute(cur, cur + 16384);                      // ahi * bhi
        } else {
            const uint32_t prv = sb + (uint32_t)((c + 3) & 3) * STAGE_BYTES;
            compute(cur, prv + 16384);                      // alo * bhi
            compute(prv, cur + 16384);                      // ahi * blo
        }
    }

    // -------- epilogue: add bias, store (scalar stores: VDIM odd =>
    //          m*VDIM+n is only guaranteed 4B-aligned) --------
    const int n0base = nt * 128 + wn * 32;
    const int m0base = mt * 128 + wm * 64;
    const int qr = lane >> 2, qc = (lane & 3) * 2;
#pragma unroll
    for (int i = 0; i < 4; i++) {
#pragma unroll
        for (int jn = 0; jn < 4; jn++) {
            int n = n0base + jn * 8 + qc;
            float b0 = (n < VDIM)     ? bias[n]     : 0.0f;
            float b1 = (n + 1 < VDIM) ? bias[n + 1] : 0.0f;
#pragma unroll
            for (int h = 0; h < 2; h++) {           // row halves r, r+8
                int m = m0base + i * 16 + qr + h * 8;
                float v0 = acc[i][jn][2 * h + 0] + b0;
                float v1 = acc[i][jn][2 * h + 1] + b1;
                size_t rb = (size_t)m * VDIM;
                if (n < VDIM)     C[rb + n]     = v0;
                if (n + 1 < VDIM) C[rb + n + 1] = v1;
            }
        }
    }
}

// ---------------------------------------------------------------------------
// Fused per-row sampler, 3 passes over the row:
//  P1: max + hist round-0          P2: expsum + hist round-1
//  P3: logp write + probs zero + hist round-2 + candidate collection
// Candidates: (key>>10) >  prefix1 -> definite top-50 member (<=49 of them)
//             (key>>10) == prefix1 -> tie bucket, filtered by thr_key after
// ---------------------------------------------------------------------------
__device__ __forceinline__ uint32_t float_key(float f) {
    uint32_t u = __float_as_uint(f);
    return (u & 0x80000000u) ? ~u : (u | 0x80000000u);
}

#define DCAP 64
#define BCAP 160
#define CAND_CAP (DCAP + BCAP)
#define STH 512

__global__ void __launch_bounds__(STH)
sampler_kernel(const float* __restrict__ logits, float* __restrict__ logp,
               float* __restrict__ probs, float* __restrict__ tokens)
{
    const int row = blockIdx.x;
    const int tid = threadIdx.x;
    const float* x = logits + (size_t)row * VDIM;
    const size_t base = (size_t)row * VDIM;

    __shared__ uint32_t hist[2048];
    __shared__ uint32_t sscan[STH];
    __shared__ float    fred[STH];
    __shared__ uint32_t s_prefix, s_rank, s_nkeep;
    __shared__ float    s_d2;
    __shared__ uint32_t dcnt, bcnt, ccnt;
    __shared__ float    dval[DCAP];   __shared__ uint32_t didx[DCAP];
    __shared__ float    bval[BCAP];   __shared__ uint32_t bidx2[BCAP];
    __shared__ float    cval[CAND_CAP]; __shared__ uint32_t cidx[CAND_CAP];
    __shared__ float    sval[CAND_CAP]; __shared__ uint32_t sidx[CAND_CAP];
    __shared__ float    ework[CAND_CAP];

    // suffix-scan over hist[0..bins) to locate the bin where the descending
    // cumulative count crosses `remaining`; sets s_prefix/s_rank.
    auto scan_cross = [&](int bins, uint32_t prefix, int lsh, uint32_t remaining) {
        const int bpt = bins / STH;
        const int b0  = tid * bpt;
        uint32_t local = 0;
        for (int j = 0; j < bpt; j++) local += hist[b0 + j];
        sscan[tid] = local;
        __syncthreads();
        for (int off = 1; off < STH; off <<= 1) {
            uint32_t v = (tid + off < STH) ? sscan[tid + off] : 0;
            __syncthreads();
            sscan[tid] += v;
            __syncthreads();
        }
        uint32_t incl  = sscan[tid];
        uint32_t after = incl - local;
        if (after < remaining && incl >= remaining) {
            uint32_t cum = after;
            for (int b = b0 + bpt - 1; b >= b0; b--) {
                cum += hist[b];
                if (cum >= remaining) {
                    s_prefix = (prefix << lsh) | (uint32_t)b;
                    s_rank   = remaining - (cum - hist[b]);
                    break;
                }
            }
        }
        __syncthreads();
    };

    // ---- P1: max + hist round-0 (bins on key>>21) ----
    for (int i = tid; i < 2048; i += STH) hist[i] = 0;
    if (tid == 0) { dcnt = 0; bcnt = 0; ccnt = 0; }
    __syncthreads();

    float m = -INFINITY;
    for (int i = tid; i < VDIM; i += STH) {
        float v = x[i];
        m = fmaxf(m, v);
        atomicAdd(&hist[float_key(v) >> 21], 1u);
    }
    fred[tid] = m; __syncthreads();
    for (int s = STH / 2; s > 0; s >>= 1) {
        if (tid < s) fred[tid] = fmaxf(fred[tid], fred[tid + s]);
        __syncthreads();
    }
    m = fred[0];
    __syncthreads();

    scan_cross(2048, 0u, 11, TOPK);
    const uint32_t prefix0 = s_prefix;
    const uint32_t rem1    = s_rank;
    __syncthreads();

    // ---- P2: expsum + hist round-1 ----
    for (int i = tid; i < 2048; i += STH) hist[i] = 0;
    __syncthreads();

    float sum = 0.0f;
    for (int i = tid; i < VDIM; i += STH) {
        float v = x[i];
        sum += expf(v - m);
        uint32_t key = float_key(v);
        if ((key >> 21) == prefix0) atomicAdd(&hist[(key >> 10) & 2047], 1u);
    }
    fred[tid] = sum; __syncthreads();
    for (int s = STH / 2; s > 0; s >>= 1) {
        if (tid < s) fred[tid] += fred[tid + s];
        __syncthreads();
    }
    const float lse = m + logf(fred[0]);
    __syncthreads();

    scan_cross(2048, prefix0, 11, rem1);
    const uint32_t prefix1 = s_prefix;   // 22-bit prefix
    const uint32_t rem2    = s_rank;
    __syncthreads();

    // ---- P3: logp + probs-zero + hist round-2 + candidate collection ----
    for (int i = tid; i < 1024; i += STH) hist[i] = 0;
    __syncthreads();

    for (int i = tid; i < VDIM; i += STH) {
        float v = x[i];
        logp[base + i]  = v - lse;
        probs[base + i] = 0.0f;
        uint32_t key = float_key(v);
        uint32_t h = key >> 10;
        if (h > prefix1) {
            uint32_t p = atomicAdd(&dcnt, 1u);
            if (p < DCAP) { dval[p] = v; didx[p] = (uint32_t)i; }
        } else if (h == prefix1) {
            uint32_t p = atomicAdd(&bcnt, 1u);
            if (p < BCAP) { bval[p] = v; bidx2[p] = (uint32_t)i; }
            atomicAdd(&hist[key & 1023], 1u);
        }
    }
    __syncthreads();

    scan_cross(1024, prefix1, 10, rem2);
    const uint32_t thr_key = s_prefix;   // full 32-bit key of rank-50 element
    __syncthreads();

    // ---- merge definite + (bucket >= thr) into combined list ----
    const int nd = (int)min(dcnt, (uint32_t)DCAP);
    const int nb = (int)min(bcnt, (uint32_t)BCAP);
    if (tid < nd) {
        uint32_t p = atomicAdd(&ccnt, 1u);
        cval[p] = dval[tid]; cidx[p] = didx[tid];
    }
    if (tid < nb && float_key(bval[tid]) >= thr_key) {
        uint32_t p = atomicAdd(&ccnt, 1u);
        cval[p] = bval[tid]; cidx[p] = bidx2[tid];
    }
    __syncthreads();
    const int n = (int)min(ccnt, (uint32_t)CAND_CAP);

    // ---- parallel rank sort (value desc, index asc) ----
    if (tid < n) {
        float v = cval[tid]; uint32_t id = cidx[tid];
        int r = 0;
        for (int j = 0; j < n; j++) {
            float vj = cval[j];
            if (vj > v || (vj == v && cidx[j] < id)) r++;
        }
        sval[r] = v; sidx[r] = id;
    }
    __syncthreads();

    if (tid < n) ework[tid] = expf(sval[tid] - sval[0]);
    __syncthreads();

    if (tid == 0) {
        float denom = 0.0f;
        for (int i = 0; i < n; i++) denom += ework[i];
        int nkeep = n; float cum = 0.0f;
        for (int i = 0; i < n; i++) {
            if (i > 0 && cum >= TOPP) { nkeep = i; break; }
            cum += ework[i] / denom;
        }
        float d2 = 0.0f;
        for (int i = 0; i < nkeep; i++) d2 += ework[i];
        s_nkeep = (uint32_t)nkeep; s_d2 = d2;
    }
    __syncthreads();
    const int nkeep = (int)s_nkeep;

    if (tid < nkeep)
        probs[base + sidx[tid]] = ework[tid] / s_d2;

    // ---- gumbel argmax over kept candidates ----
    float best = -INFINITY; uint32_t bi = 0xFFFFFFFFu;
    if (tid < nkeep) {
        float g = gumbel_at((unsigned long long)row * VDIM + sidx[tid]);
        best = sval[tid] + g;
        bi = sidx[tid];
    }
    fred[tid] = best; sscan[tid] = bi;
    __syncthreads();
    for (int s = STH / 2; s > 0; s >>= 1) {
        if (tid < s) {
            float f2 = fred[tid + s]; uint32_t i2 = sscan[tid + s];
            if (f2 > fred[tid] || (f2 == fred[tid] && i2 < sscan[tid])) {
                fred[tid] = f2; sscan[tid] = i2;
            }
        }
        __syncthreads();
    }
    if (tid == 0) tokens[row] = (float)sscan[0];
}

// ---------------------------------------------------------------------------
// Launch
// ---------------------------------------------------------------------------
extern "C" void kernel_launch(void* const* d_in, const int* in_sizes, int n_in,
                              void* d_out, int out_size)
{
    const float* Pr   = (const float*)d_in[0];
    const float* Pi   = (const float*)d_in[1];
    const float* Wr   = (const float*)d_in[2];
    const float* Wi   = (const float*)d_in[3];
    const float* bias = (const float*)d_in[4];

    float* out    = (float*)d_out;
    float* logits = out;
    float* logp   = out + BSV;
    float* tokens = out + 2 * BSV;
    float* probs  = out + 2 * BSV + BDIM;

    cudaFuncSetAttribute(gemm_mma_kernel,
                         cudaFuncAttributeMaxDynamicSharedMemorySize, GEMM_SMEM);

    convA_kernel<<<512, 256>>>(Pr, Pi);
    convB_kernel<<<NPAD, 256>>>(Wr, Wi);
    gemm_mma_kernel<<<NT * 4, 256, GEMM_SMEM>>>(bias, logits);
    sampler_kernel<<<BDIM, STH>>>(logits, logp, probs, tokens);
}

// round 16
// speedup vs baseline: 1.1210x; 1.1210x over previous
#include <cuda_runtime.h>
#include <cuda_bf16.h>
#include <math.h>
#include <stdint.h>
#include <stddef.h>

// BornCollapseSampler — bf16 split-precision GEMM via mma.sync (HMMA.16816)
// + fused 3-pass sampler.
// R15: revert GEMM to 3-buffer ring @ occupancy 2 (R14's occ-1 4-ring was a
//      ~120us regression: whole-SM syncs, no co-CTA cover, 2x waves).
//      Keep one safe piece: EVEN iterations issue prefetch BEFORE compute
//      (slot (c+2)%3 != c%3, sealed by prior odd iter's 2nd sync).
//      Sampler: R14 fused 3-pass version (measured 147.6us), unchanged.
//
// Output layout (float32): [0,BSV) logits | [BSV,2BSV) log_probs |
//                          [2BSV,2BSV+512) tokens | then probs.

#define BDIM 512
#define VDIM 50257
#define KDIM 1024
#define TOPK 50
#define TOPP 0.95f
#define THREEFRY_PARTITIONABLE 1

#define NT   393            // n tiles of 128 (pad to 50304)
#define NPAD (NT * 128)
#define KC   32             // k chunks of 64 bf16 per 2048-col half

static const long long BSV = (long long)BDIM * VDIM;

// scratch: SW128-swizzled tile blocks, 128 rows x 64 bf16 = 16KB = 1024 uint4
__device__ uint4 g_Ahi[KC * 4 * 1024];                 // [kc][m_tile][block]
__device__ uint4 g_Alo[KC * 4 * 1024];
__device__ uint4 g_Bhi[(size_t)NT * KC * 1024];        // [nt][kc][block]
__device__ uint4 g_Blo[(size_t)NT * KC * 1024];

// ---------------------------------------------------------------------------
// threefry2x32 key (0,42)
// ---------------------------------------------------------------------------
__device__ __forceinline__ uint32_t rotl32(uint32_t x, int r) {
    return (x << r) | (x >> (32 - r));
}
__device__ __forceinline__ uint2 tf2x32(uint32_t x0, uint32_t x1) {
    const uint32_t k0 = 0u, k1 = 42u;
    const uint32_t k2 = k0 ^ k1 ^ 0x1BD11BDAu;
    x0 += k0; x1 += k1;
#define TFR(r) { x0 += x1; x1 = rotl32(x1, r); x1 ^= x0; }
    TFR(13) TFR(15) TFR(26) TFR(6)   x0 += k1; x1 += k2 + 1u;
    TFR(17) TFR(29) TFR(16) TFR(24)  x0 += k2; x1 += k0 + 2u;
    TFR(13) TFR(15) TFR(26) TFR(6)   x0 += k0; x1 += k1 + 3u;
    TFR(17) TFR(29) TFR(16) TFR(24)  x0 += k1; x1 += k2 + 4u;
    TFR(13) TFR(15) TFR(26) TFR(6)   x0 += k2; x1 += k0 + 5u;
#undef TFR
    return make_uint2(x0, x1);
}
__device__ __forceinline__ float gumbel_at(unsigned long long i) {
    uint32_t bits;
#if THREEFRY_PARTITIONABLE
    uint2 o = tf2x32((uint32_t)(i >> 32), (uint32_t)i);
    bits = o.x ^ o.y;
#else
    const unsigned long long HALF = ((unsigned long long)BDIM * VDIM) / 2ull;
    if (i < HALF) { uint2 o = tf2x32((uint32_t)i, (uint32_t)(i + HALF)); bits = o.x; }
    else          { uint2 o = tf2x32((uint32_t)(i - HALF), (uint32_t)i); bits = o.y; }
#endif
    float f = __uint_as_float((bits >> 9) | 0x3f800000u) - 1.0f;
    float u = fmaxf(f, 1.1754943508222875e-38f);
    return -logf(-logf(u));
}

// ---------------------------------------------------------------------------
// Conversion: fp32 -> (hi, lo) bf16 into SW128-swizzled tile blocks
// ---------------------------------------------------------------------------
__device__ __forceinline__ uint32_t sw128(uint32_t b) { return b ^ ((b >> 3) & 0x70u); }

union U16x8 { uint4 v; unsigned short s[8]; };

__global__ void __launch_bounds__(256) convA_kernel(const float* __restrict__ Pr,
                                                    const float* __restrict__ Pi)
{
    int g = blockIdx.x * 256 + threadIdx.x;   // 512 rows x 256 groups
    int row = g >> 8, grp = g & 255;
    int col0 = grp * 8;
    U16x8 uh, ul;
#pragma unroll
    for (int j = 0; j < 8; j++) {
        int c = col0 + j;
        float x = (c < KDIM) ? Pr[row * KDIM + c] : Pi[row * KDIM + c - KDIM];
        __nv_bfloat16 h = __float2bfloat16(x);
        __nv_bfloat16 l = __float2bfloat16(x - __bfloat162float(h));
        uh.s[j] = *reinterpret_cast<unsigned short*>(&h);
        ul.s[j] = *reinterpret_cast<unsigned short*>(&l);
    }
    int kc = col0 >> 6, cc = col0 & 63, m = row >> 7, r = row & 127;
    uint32_t byte = (uint32_t)(r * 128 + cc * 2);
    uint32_t unit = sw128(byte) >> 4;
    size_t idx = (size_t)(kc * 4 + m) * 1024 + unit;
    g_Ahi[idx] = uh.v;
    g_Alo[idx] = ul.v;
}

__global__ void __launch_bounds__(256) convB_kernel(const float* __restrict__ Wr,
                                                    const float* __restrict__ Wi)
{
    int row = blockIdx.x;          // 0..NPAD-1
    int col0 = threadIdx.x * 8;
    bool valid = (row < VDIM);
    U16x8 uh, ul;
#pragma unroll
    for (int j = 0; j < 8; j++) {
        int c = col0 + j;
        float x = 0.0f;
        if (valid) x = (c < KDIM) ? Wr[(size_t)row * KDIM + c]
                                  : Wi[(size_t)row * KDIM + c - KDIM];
        __nv_bfloat16 h = __float2bfloat16(x);
        __nv_bfloat16 l = __float2bfloat16(x - __bfloat162float(h));
        uh.s[j] = *reinterpret_cast<unsigned short*>(&h);
        ul.s[j] = *reinterpret_cast<unsigned short*>(&l);
    }
    int nt = row >> 7, kc = col0 >> 6, cc = col0 & 63, r = row & 127;
    uint32_t byte = (uint32_t)(r * 128 + cc * 2);
    uint32_t unit = sw128(byte) >> 4;
    size_t idx = (size_t)(nt * KC + kc) * 1024 + unit;
    g_Bhi[idx] = uh.v;
    g_Blo[idx] = ul.v;
}

// ---------------------------------------------------------------------------
// GEMM via mma.sync m16n8k16 bf16
// CTA: 128(M) x 128(N), 8 warps as 2(M) x 4(N), warp tile 64x32, occupancy 2.
// 3-buffer cp.async ring, depth-2 prefetch.
//   even c: wait, sync, issue(c+2) [writes (c+2)%3 != c%3], compute cur.
//   odd  c: wait, sync, compute(cur,prv), sync, issue(c+2) [writes prv slot].
// Chunks: even c -> {Ahi,Bhi}[kc] compute ahi*bhi;
// odd c -> {Alo,Blo}[kc] compute alo*bhi(prev buf) + ahi(prev buf)*blo.
// ---------------------------------------------------------------------------
__device__ __forceinline__ uint32_t smem_u32(const void* p) {
    uint32_t a;
    asm("{ .reg .u64 t; cvta.to.shared.u64 t, %1; cvt.u32.u64 %0, t; }"
        : "=r"(a) : "l"(p));
    return a;
}
__device__ __forceinline__ void cp16(uint32_t dst, const void* src) {
    asm volatile("cp.async.cg.shared.global [%0], [%1], 16;"
                 :: "r"(dst), "l"(src) : "memory");
}
__device__ __forceinline__ void cp_commit() {
    asm volatile("cp.async.commit_group;" ::: "memory");
}
__device__ __forceinline__ void ldsm4(uint32_t* r, uint32_t addr) {
    asm volatile("ldmatrix.sync.aligned.m8n8.x4.shared.b16 {%0,%1,%2,%3}, [%4];"
                 : "=r"(r[0]), "=r"(r[1]), "=r"(r[2]), "=r"(r[3]) : "r"(addr));
}
__device__ __forceinline__ void mma16816(float* d, const uint32_t* a,
                                         uint32_t b0, uint32_t b1) {
    asm volatile(
        "mma.sync.aligned.m16n8k16.row.col.f32.bf16.bf16.f32 "
        "{%0,%1,%2,%3}, {%4,%5,%6,%7}, {%8,%9}, {%0,%1,%2,%3};"
        : "+f"(d[0]), "+f"(d[1]), "+f"(d[2]), "+f"(d[3])
        : "r"(a[0]), "r"(a[1]), "r"(a[2]), "r"(a[3]), "r"(b0), "r"(b1));
}

#define STAGE_BYTES 32768
#define GEMM_SMEM (3 * STAGE_BYTES)    // 98304

__global__ void __launch_bounds__(256, 2)
gemm_mma_kernel(const float* __restrict__ bias, float* __restrict__ C)
{
    extern __shared__ char smem[];
    const uint32_t sb = smem_u32(smem);
    const int tid  = threadIdx.x;
    const int lane = tid & 31, w = tid >> 5;
    const int wm = w & 1, wn = w >> 1;
    const int nt = blockIdx.x >> 2, mt = blockIdx.x & 3;

    float acc[4][4][4];
#pragma unroll
    for (int i = 0; i < 4; i++)
#pragma unroll
        for (int j = 0; j < 4; j++)
#pragma unroll
            for (int r = 0; r < 4; r++) acc[i][j][r] = 0.0f;

    // per-lane ldmatrix row offsets
    const int rlo = lane & 15;           // row within 16
    const int khalf = (lane >> 4) * 16;  // 16B col half

    // -------- async chunk issuer --------
    auto issue = [&](int c) {
        const int kc = c >> 1;
        const uint4* As = ((c & 1) ? g_Alo : g_Ahi) + (size_t)(kc * 4 + mt) * 1024;
        const uint4* Bs = ((c & 1) ? g_Blo : g_Bhi) + ((size_t)nt * KC + kc) * 1024;
        const uint32_t d = sb + (uint32_t)(c % 3) * STAGE_BYTES;
#pragma unroll
        for (int i = 0; i < 4; i++) {
            int s = tid + i * 256;
            cp16(d + s * 16, As + s);
            cp16(d + 16384 + s * 16, Bs + s);
        }
        cp_commit();
    };

    // -------- compute one 64-k-bf16 pass --------
    auto compute = [&](uint32_t aBase, uint32_t bBase) {
#pragma unroll
        for (int kk = 0; kk < 4; kk++) {
            const uint32_t off = kk * 32 + khalf;
            uint32_t aR[4][4], bR[2][4];
#pragma unroll
            for (int i = 0; i < 4; i++) {
                int row = wm * 64 + i * 16 + rlo;
                uint32_t addr = aBase + row * 128 + (off ^ ((row & 7) << 4));
                ldsm4(aR[i], addr);
            }
#pragma unroll
            for (int j = 0; j < 2; j++) {
                int row = wn * 32 + j * 16 + rlo;
                uint32_t addr = bBase + row * 128 + (off ^ ((row & 7) << 4));
                ldsm4(bR[j], addr);
            }
#pragma unroll
            for (int i = 0; i < 4; i++)
#pragma unroll
                for (int jn = 0; jn < 4; jn++)
                    mma16816(acc[i][jn], aR[i],
                             bR[jn >> 1][jn & 1], bR[jn >> 1][2 + (jn & 1)]);
        }
    };

    issue(0);
    issue(1);

    for (int c = 0; c < 64; c++) {
        if (c < 63) asm volatile("cp.async.wait_group 1;" ::: "memory");
        else        asm volatile("cp.async.wait_group 0;" ::: "memory");
        __syncthreads();

        const uint32_t cur = sb + (uint32_t)(c % 3) * STAGE_BYTES;
        if ((c & 1) == 0) {
            // even: prefetch first (slot (c+2)%3 != c%3; sealed by prior odd
            // iteration's post-compute sync), then compute ahi*bhi.
            if (c + 2 < 64) issue(c + 2);
            compute(cur, cur + 16384);
        } else {
            // odd: issue(c+2) would overwrite prv — must follow compute+sync.
            const uint32_t prv = sb + (uint32_t)((c + 2) % 3) * STAGE_BYTES;
            compute(cur, prv + 16384);                      // alo * bhi
            compute(prv, cur + 16384);                      // ahi * blo
            __syncthreads();
            if (c + 2 < 64) issue(c + 2);
        }
    }

    // -------- epilogue: add bias, store (scalar stores: VDIM odd =>
    //          m*VDIM+n is only guaranteed 4B-aligned) --------
    const int n0base = nt * 128 + wn * 32;
    const int m0base = mt * 128 + wm * 64;
    const int qr = lane >> 2, qc = (lane & 3) * 2;
#pragma unroll
    for (int i = 0; i < 4; i++) {
#pragma unroll
        for (int jn = 0; jn < 4; jn++) {
            int n = n0base + jn * 8 + qc;
            float b0 = (n < VDIM)     ? bias[n]     : 0.0f;
            float b1 = (n + 1 < VDIM) ? bias[n + 1] : 0.0f;
#pragma unroll
            for (int h = 0; h < 2; h++) {           // row halves r, r+8
                int m = m0base + i * 16 + qr + h * 8;
                float v0 = acc[i][jn][2 * h + 0] + b0;
                float v1 = acc[i][jn][2 * h + 1] + b1;
                size_t rb = (size_t)m * VDIM;
                if (n < VDIM)     C[rb + n]     = v0;
                if (n + 1 < VDIM) C[rb + n + 1] = v1;
            }
        }
    }
}

// ---------------------------------------------------------------------------
// Fused per-row sampler, 3 passes over the row (R14, measured 147.6us):
//  P1: max + hist round-0          P2: expsum + hist round-1
//  P3: logp write + probs zero + hist round-2 + candidate collection
// ---------------------------------------------------------------------------
__device__ __forceinline__ uint32_t float_key(float f) {
    uint32_t u = __float_as_uint(f);
    return (u & 0x80000000u) ? ~u : (u | 0x80000000u);
}

#define DCAP 64
#define BCAP 160
#define CAND_CAP (DCAP + BCAP)
#define STH 512

__global__ void __launch_bounds__(STH)
sampler_kernel(const float* __restrict__ logits, float* __restrict__ logp,
               float* __restrict__ probs, float* __restrict__ tokens)
{
    const int row = blockIdx.x;
    const int tid = threadIdx.x;
    const float* x = logits + (size_t)row * VDIM;
    const size_t base = (size_t)row * VDIM;

    __shared__ uint32_t hist[2048];
    __shared__ uint32_t sscan[STH];
    __shared__ float    fred[STH];
    __shared__ uint32_t s_prefix, s_rank, s_nkeep;
    __shared__ float    s_d2;
    __shared__ uint32_t dcnt, bcnt, ccnt;
    __shared__ float    dval[DCAP];   __shared__ uint32_t didx[DCAP];
    __shared__ float    bval[BCAP];   __shared__ uint32_t bidx2[BCAP];
    __shared__ float    cval[CAND_CAP]; __shared__ uint32_t cidx[CAND_CAP];
    __shared__ float    sval[CAND_CAP]; __shared__ uint32_t sidx[CAND_CAP];
    __shared__ float    ework[CAND_CAP];

    auto scan_cross = [&](int bins, uint32_t prefix, int lsh, uint32_t remaining) {
        const int bpt = bins / STH;
        const int b0  = tid * bpt;
        uint32_t local = 0;
        for (int j = 0; j < bpt; j++) local += hist[b0 + j];
        sscan[tid] = local;
        __syncthreads();
        for (int off = 1; off < STH; off <<= 1) {
            uint32_t v = (tid + off < STH) ? sscan[tid + off] : 0;
            __syncthreads();
            sscan[tid] += v;
            __syncthreads();
        }
        uint32_t incl  = sscan[tid];
        uint32_t after = incl - local;
        if (after < remaining && incl >= remaining) {
            uint32_t cum = after;
            for (int b = b0 + bpt - 1; b >= b0; b--) {
                cum += hist[b];
                if (cum >= remaining) {
                    s_prefix = (prefix << lsh) | (uint32_t)b;
                    s_rank   = remaining - (cum - hist[b]);
                    break;
                }
            }
        }
        __syncthreads();
    };

    // ---- P1: max + hist round-0 (bins on key>>21) ----
    for (int i = tid; i < 2048; i += STH) hist[i] = 0;
    if (tid == 0) { dcnt = 0; bcnt = 0; ccnt = 0; }
    __syncthreads();

    float m = -INFINITY;
    for (int i = tid; i < VDIM; i += STH) {
        float v = x[i];
        m = fmaxf(m, v);
        atomicAdd(&hist[float_key(v) >> 21], 1u);
    }
    fred[tid] = m; __syncthreads();
    for (int s = STH / 2; s > 0; s >>= 1) {
        if (tid < s) fred[tid] = fmaxf(fred[tid], fred[tid + s]);
        __syncthreads();
    }
    m = fred[0];
    __syncthreads();

    scan_cross(2048, 0u, 11, TOPK);
    const uint32_t prefix0 = s_prefix;
    const uint32_t rem1    = s_rank;
    __syncthreads();

    // ---- P2: expsum + hist round-1 ----
    for (int i = tid; i < 2048; i += STH) hist[i] = 0;
    __syncthreads();

    float sum = 0.0f;
    for (int i = tid; i < VDIM; i += STH) {
        float v = x[i];
        sum += expf(v - m);
        uint32_t key = float_key(v);
        if ((key >> 21) == prefix0) atomicAdd(&hist[(key >> 10) & 2047], 1u);
    }
    fred[tid] = sum; __syncthreads();
    for (int s = STH / 2; s > 0; s >>= 1) {
        if (tid < s) fred[tid] += fred[tid + s];
        __syncthreads();
    }
    const float lse = m + logf(fred[0]);
    __syncthreads();

    scan_cross(2048, prefix0, 11, rem1);
    const uint32_t prefix1 = s_prefix;   // 22-bit prefix
    const uint32_t rem2    = s_rank;
    __syncthreads();

    // ---- P3: logp + probs-zero + hist round-2 + candidate collection ----
    for (int i = tid; i < 1024; i += STH) hist[i] = 0;
    __syncthreads();

    for (int i = tid; i < VDIM; i += STH) {
        float v = x[i];
        logp[base + i]  = v - lse;
        probs[base + i] = 0.0f;
        uint32_t key = float_key(v);
        uint32_t h = key >> 10;
        if (h > prefix1) {
            uint32_t p = atomicAdd(&dcnt, 1u);
            if (p < DCAP) { dval[p] = v; didx[p] = (uint32_t)i; }
        } else if (h == prefix1) {
            uint32_t p = atomicAdd(&bcnt, 1u);
            if (p < BCAP) { bval[p] = v; bidx2[p] = (uint32_t)i; }
            atomicAdd(&hist[key & 1023], 1u);
        }
    }
    __syncthreads();

    scan_cross(1024, prefix1, 10, rem2);
    const uint32_t thr_key = s_prefix;   // full 32-bit key of rank-50 element
    __syncthreads();

    // ---- merge definite + (bucket >= thr) into combined list ----
    const int nd = (int)min(dcnt, (uint32_t)DCAP);
    const int nb = (int)min(bcnt, (uint32_t)BCAP);
    if (tid < nd) {
        uint32_t p = atomicAdd(&ccnt, 1u);
        cval[p] = dval[tid]; cidx[p] = didx[tid];
    }
    if (tid < nb && float_key(bval[tid]) >= thr_key) {
        uint32_t p = atomicAdd(&ccnt, 1u);
        cval[p] = bval[tid]; cidx[p] = bidx2[tid];
    }
    __syncthreads();
    const int n = (int)min(ccnt, (uint32_t)CAND_CAP);

    // ---- parallel rank sort (value desc, index asc) ----
    if (tid < n) {
        float v = cval[tid]; uint32_t id = cidx[tid];
        int r = 0;
        for (int j = 0; j < n; j++) {
            float vj = cval[j];
            if (vj > v || (vj == v && cidx[j] < id)) r++;
        }
        sval[r] = v; sidx[r] = id;
    }
    __syncthreads();

    if (tid < n) ework[tid] = expf(sval[tid] - sval[0]);
    __syncthreads();

    if (tid == 0) {
        float denom = 0.0f;
        for (int i = 0; i < n; i++) denom += ework[i];
        int nkeep = n; float cum = 0.0f;
        for (int i = 0; i < n; i++) {
            if (i > 0 && cum >= TOPP) { nkeep = i; break; }
            cum += ework[i] / denom;
        }
        float d2 = 0.0f;
        for (int i = 0; i < nkeep; i++) d2 += ework[i];
        s_nkeep = (uint32_t)nkeep; s_d2 = d2;
    }
    __syncthreads();
    const int nkeep = (int)s_nkeep;

    if (tid < nkeep)
        probs[base + sidx[tid]] = ework[tid] / s_d2;

    // ---- gumbel argmax over kept candidates ----
    float best = -INFINITY; uint32_t bi = 0xFFFFFFFFu;
    if (tid < nkeep) {
        float g = gumbel_at((unsigned long long)row * VDIM + sidx[tid]);
        best = sval[tid] + g;
        bi = sidx[tid];
    }
    fred[tid] = best; sscan[tid] = bi;
    __syncthreads();
    for (int s = STH / 2; s > 0; s >>= 1) {
        if (tid < s) {
            float f2 = fred[tid + s]; uint32_t i2 = sscan[tid + s];
            if (f2 > fred[tid] || (f2 == fred[tid] && i2 < sscan[tid])) {
                fred[tid] = f2; sscan[tid] = i2;
            }
        }
        __syncthreads();
    }
    if (tid == 0) tokens[row] = (float)sscan[0];
}

// ---------------------------------------------------------------------------
// Launch
// ---------------------------------------------------------------------------
extern "C" void kernel_launch(void* const* d_in, const int* in_sizes, int n_in,
                              void* d_out, int out_size)
{
    const float* Pr   = (const float*)d_in[0];
    const float* Pi   = (const float*)d_in[1];
    const float* Wr   = (const float*)d_in[2];
    const float* Wi   = (const float*)d_in[3];
    const float* bias = (const float*)d_in[4];

    float* out    = (float*)d_out;
    float* logits = out;
    float* logp   = out + BSV;
    float* tokens = out + 2 * BSV;
    float* probs  = out + 2 * BSV + BDIM;

    cudaFuncSetAttribute(gemm_mma_kernel,
                         cudaFuncAttributeMaxDynamicSharedMemorySize, GEMM_SMEM);

    convA_kernel<<<512, 256>>>(Pr, Pi);
    convB_kernel<<<NPAD, 256>>>(Wr, Wi);
    gemm_mma_kernel<<<NT * 4, 256, GEMM_SMEM>>>(bias, logits);
    sampler_kernel<<<BDIM, STH>>>(logits, logp, probs, tokens);
}